// round 14
// baseline (speedup 1.0000x reference)
#include <cuda_runtime.h>
#include <math.h>
#include <limits.h>

// CRF loss: out[b] = logZ(b) - label_score(b).  B=512, S=512, L=128.
//
// Scaled linear-space forward recursion, TWO adjacent-length batches per
// 512-thread block at 2 CTAs/SM (32 warps/SM). Lane bits do triple duty:
//   reads:  rg = l&7 -> rows [16rg,16rg+16): 4x LDS.128/batch, 8 distinct
//           16B lines/warp = 1 wavefront each.
//   route:  owner-directed butterfly over bits 0..2 (4 shfl/pair-step)
//           lands the full (batch=l&1, colhalf=(l>>1)&1) sum on its owner.
//   cols:   cs = (l>>3)&3 -> jc = 4w+cs; thread covers cols {jc, jc+64}
//           with E = 2x8 f32x2 regs (32 values, one E copy per block).
// Every lane owns one (g, jo) scalar stream (dup lanes mirror it); only
// dup==0 stores U. Bank-engineered u_sh[2][2][136] (skew +4 at jo>=64,
// batch stride 136): reads AND stores single-wavefront. ONE __syncthreads
// per step. Pairs sorted longest-first; co-residency remap pairs heavy
// blocks (bid<148) with light partners on the same SM.

#define LDIM 128

__device__ int d_perm[1024];

__device__ __forceinline__ unsigned long long pack_f32x2(float lo, float hi) {
    unsigned long long r;
    asm("mov.b64 %0, {%1, %2};" : "=l"(r) : "f"(lo), "f"(hi));
    return r;
}
__device__ __forceinline__ void unpack_f32x2(unsigned long long v, float& lo, float& hi) {
    asm("mov.b64 {%0, %1}, %2;" : "=f"(lo), "=f"(hi) : "l"(v));
}
__device__ __forceinline__ unsigned long long fma_f32x2(unsigned long long a,
                                                        unsigned long long b,
                                                        unsigned long long c) {
    unsigned long long d;
    asm("fma.rn.f32x2 %0, %1, %2, %3;" : "=l"(d) : "l"(a), "l"(b), "l"(c));
    return d;
}
__device__ __forceinline__ float rcp_approx(float x) {
    float r;
    asm("rcp.approx.ftz.f32 %0, %1;" : "=f"(r) : "f"(x));
    return r;
}
__device__ __forceinline__ float hsum1(unsigned long long a) {
    float lo, hi;
    unpack_f32x2(a, lo, hi);
    return lo + hi;
}

// ------------- longest-first permutation (bitonic, 1 block) ---------------
__global__ void sort_len_kernel(const int* __restrict__ length, int B, int S)
{
    __shared__ int key[1024];
    __shared__ int val[1024];
    const int t = threadIdx.x;

    int k = INT_MAX;
    if (t < B) {
        int L = length[t];
        L = L < 1 ? 1 : (L > S ? S : L);
        k = -L;               // ascending on -len => longest first
    }
    key[t] = k;
    val[t] = t;
    __syncthreads();

    for (int kk = 2; kk <= 1024; kk <<= 1) {
        for (int s = kk >> 1; s > 0; s >>= 1) {
            int p = t ^ s;
            if (p > t) {
                bool up = ((t & kk) == 0);
                int kt = key[t], kp = key[p];
                if ((kt > kp) == up) {
                    key[t] = kp; key[p] = kt;
                    int vt = val[t]; val[t] = val[p]; val[p] = vt;
                }
            }
            __syncthreads();
        }
    }
    if (t < B) d_perm[t] = val[t];
}

// ------------------------------ main kernel --------------------------------
__global__ __launch_bounds__(512, 2)
void crf_forward_kernel(const float* __restrict__ input,
                        const int*   __restrict__ label,
                        const int*   __restrict__ length,
                        const float* __restrict__ trans,
                        float* __restrict__ out,
                        int S, int B, int npairs, int nfirst)
{
    __shared__ __align__(16) float u_sh[2][2][136];   // [buf][g][skewed col]
    __shared__ float wred[2][16];
    __shared__ float wlog[2][16];
    __shared__ float s_x00[2];
    __shared__ float s_ls[2];

    const int tid = threadIdx.x;
    const int w   = tid >> 5;            // warp 0..15
    const int l   = tid & 31;
    const int rg  = l & 7;               // rows [16rg, 16rg+16)
    const int g   = l & 1;               // owned batch (post-routing)
    const int myc = (l >> 1) & 1;        // owned column half
    const int dup = (l >> 2) & 1;        // duplicate-owner flag
    const int cs  = (l >> 3) & 3;        // column slot
    const int jc  = 4 * w + cs;          // 0..63
    const int jo  = jc + (myc << 6);     // owned column 0..127
    const int sidx = jo + ((jo >> 6) << 2);          // skewed store index
    const int qi   = 4 * rg + (rg >> 2);             // ull2 read base

    const int bid = blockIdx.x;
    const int pid = (bid < nfirst) ? bid : (npairs - 1 - (bid - nfirst));

    const int  b0   = d_perm[2 * pid];
    const bool has1 = (2 * pid + 1 < B);
    const int  b1   = has1 ? d_perm[2 * pid + 1] : b0;

    int len0 = length[b0]; len0 = len0 < 1 ? 1 : (len0 > S ? S : len0);
    int len1 = len0;
    if (has1) { len1 = length[b1]; len1 = len1 < 1 ? 1 : (len1 > S ? S : len1); }
    // sorted order: len0 >= len1.

    const float* xb0 = input + (size_t)b0 * S * LDIM;
    const float* xb1 = input + (size_t)b1 * S * LDIM;
    const int    lenown = g ? len1 : len0;

    // ---------------- label scores (both batches) ----------------------
    #pragma unroll
    for (int gg = 0; gg < 2; gg++) {
        const float* xb = gg ? xb1 : xb0;
        const int* labb = label + (size_t)(gg ? b1 : b0) * S;
        const int  len  = gg ? (has1 ? len1 : 0) : len0;
        float ls = 0.f;
        for (int t = tid; t < len; t += 512) {
            int lab = labb[t];
            ls += xb[(size_t)t * LDIM + lab];
            if (t + 1 < len) ls += trans[lab * LDIM + labb[t + 1]];
        }
        #pragma unroll
        for (int o = 16; o > 0; o >>= 1)
            ls += __shfl_xor_sync(0xffffffffu, ls, o);
        if (l == 0) wred[gg][w] = ls;
    }
    __syncthreads();
    if (tid < 2) {
        float acc = 0.f;
        #pragma unroll
        for (int i = 0; i < 16; i++) acc += wred[tid][i];
        s_ls[tid] = acc;
    }

    // ---- E rows [16rg,16rg+16) of cols {jc, jc+64}: 16 f32x2 regs -----
    unsigned long long E2[2][8];
    #pragma unroll
    for (int c = 0; c < 2; c++) {
        int col = jc + (c << 6);
        #pragma unroll
        for (int k = 0; k < 8; k++) {
            int r0 = 16 * rg + 2 * k;
            E2[c][k] = pack_f32x2(__expf(trans[r0 * LDIM + col]),
                                  __expf(trans[(r0 + 1) * LDIM + col]));
        }
    }

    // ---------------- init U + prefetch --------------------------------
    const float* pj = (g ? xb1 : xb0) + jo;
    float x0 = pj[0];
    if (tid < 2) s_x00[tid] = x0;     // tid0: g0 jo0; tid1: g1 jo0
    __syncthreads();
    float U = __expf(x0 - s_x00[g]);
    if (dup == 0) u_sh[0][g][sidx] = U;

    const int omax = (lenown - 1) << 7;
    int oB = 256 < omax ? 256 : omax;            // offset of xB (t=2)
    int oA = 128 < omax ? 128 : omax;
    float xA = pj[oA];                            // x for t=1
    float xB = pj[oB];                            // x for t=2

    float alog = 0.f;
    __syncthreads();

    int cur = 0;

    // ---------------- forward recursion: t = 1 .. len0-1 ----------------
    for (int t = 1; t < len0; t++) {
        const float r  = rcp_approx(u_sh[cur][g][0]);
        const float ex = __expf(xA);

        xA = xB;
        oB = (oB + 128) < omax ? (oB + 128) : omax;
        xB = pj[oB];

        // partial GEMV, batch-sequential to cap live registers
        float p00, p01, p10, p11;
        {
            const ulonglong2* q = (const ulonglong2*)(&u_sh[cur][0][0]) + qi;
            ulonglong2 u0 = q[0], u1 = q[1], u2 = q[2], u3 = q[3];
            unsigned long long a0 = 0ull, a1 = 0ull;
            a0 = fma_f32x2(u0.x, E2[0][0], a0);
            a1 = fma_f32x2(u0.x, E2[1][0], a1);
            a0 = fma_f32x2(u0.y, E2[0][1], a0);
            a1 = fma_f32x2(u0.y, E2[1][1], a1);
            a0 = fma_f32x2(u1.x, E2[0][2], a0);
            a1 = fma_f32x2(u1.x, E2[1][2], a1);
            a0 = fma_f32x2(u1.y, E2[0][3], a0);
            a1 = fma_f32x2(u1.y, E2[1][3], a1);
            a0 = fma_f32x2(u2.x, E2[0][4], a0);
            a1 = fma_f32x2(u2.x, E2[1][4], a1);
            a0 = fma_f32x2(u2.y, E2[0][5], a0);
            a1 = fma_f32x2(u2.y, E2[1][5], a1);
            a0 = fma_f32x2(u3.x, E2[0][6], a0);
            a1 = fma_f32x2(u3.x, E2[1][6], a1);
            a0 = fma_f32x2(u3.y, E2[0][7], a0);
            a1 = fma_f32x2(u3.y, E2[1][7], a1);
            p00 = hsum1(a0);
            p01 = hsum1(a1);
        }
        {
            const ulonglong2* q = (const ulonglong2*)(&u_sh[cur][1][0]) + qi;
            ulonglong2 u0 = q[0], u1 = q[1], u2 = q[2], u3 = q[3];
            unsigned long long a0 = 0ull, a1 = 0ull;
            a0 = fma_f32x2(u0.x, E2[0][0], a0);
            a1 = fma_f32x2(u0.x, E2[1][0], a1);
            a0 = fma_f32x2(u0.y, E2[0][1], a0);
            a1 = fma_f32x2(u0.y, E2[1][1], a1);
            a0 = fma_f32x2(u1.x, E2[0][2], a0);
            a1 = fma_f32x2(u1.x, E2[1][2], a1);
            a0 = fma_f32x2(u1.y, E2[0][3], a0);
            a1 = fma_f32x2(u1.y, E2[1][3], a1);
            a0 = fma_f32x2(u2.x, E2[0][4], a0);
            a1 = fma_f32x2(u2.x, E2[1][4], a1);
            a0 = fma_f32x2(u2.y, E2[0][5], a0);
            a1 = fma_f32x2(u2.y, E2[1][5], a1);
            a0 = fma_f32x2(u3.x, E2[0][6], a0);
            a1 = fma_f32x2(u3.x, E2[1][6], a1);
            a0 = fma_f32x2(u3.y, E2[0][7], a0);
            a1 = fma_f32x2(u3.y, E2[1][7], a1);
            p10 = hsum1(a0);
            p11 = hsum1(a1);
        }

        // owner-directed butterfly over lane bits 0..2 (4 shfl total)
        // stage xor1: keep own batch's two cols, receive them from partner
        float k0 = g ? p10 : p00;
        float m0 = g ? p00 : p10;
        float k1 = g ? p11 : p01;
        float m1 = g ? p01 : p11;
        k0 += __shfl_xor_sync(0xffffffffu, m0, 1);
        k1 += __shfl_xor_sync(0xffffffffu, m1, 1);
        // stage xor2: keep own column half
        float kk = myc ? k1 : k0;
        float mm = myc ? k0 : k1;
        kk += __shfl_xor_sync(0xffffffffu, mm, 2);
        // stage xor4: duplicates hold the same stream
        kk += __shfl_xor_sync(0xffffffffu, kk, 4);

        float Un = kk * (r * ex);
        U = (t < lenown) ? Un : U;
        if (dup == 0) u_sh[cur ^ 1][g][sidx] = U;
        if (l < 2 && w == (t & 15) && t < lenown)
            alog += __logf(r);                     // lane0:g0, lane1:g1
        cur ^= 1;
        __syncthreads();
    }

    // ---------------- outputs ------------------------------------------
    float es0 = (g == 0 && dup == 0) ? U : 0.f;
    float es1 = (g == 1 && dup == 0) ? U : 0.f;
    #pragma unroll
    for (int oo = 16; oo > 0; oo >>= 1) {
        es0 += __shfl_xor_sync(0xffffffffu, es0, oo);
        es1 += __shfl_xor_sync(0xffffffffu, es1, oo);
    }
    if (l == 0) { wred[0][w] = es0; wred[1][w] = es1; wlog[0][w] = alog; }
    if (l == 1) { wlog[1][w] = alog; }
    __syncthreads();
    if (tid == 0) {
        float ss0 = 0.f, al0 = 0.f;
        #pragma unroll
        for (int i = 0; i < 16; i++) { ss0 += wred[0][i]; al0 += wlog[0][i]; }
        out[b0] = s_x00[0] - al0 + logf(ss0) - s_ls[0];
        if (has1) {
            float ss1 = 0.f, al1 = 0.f;
            #pragma unroll
            for (int i = 0; i < 16; i++) { ss1 += wred[1][i]; al1 += wlog[1][i]; }
            out[b1] = s_x00[1] - al1 + logf(ss1) - s_ls[1];
        }
    }
}

extern "C" void kernel_launch(void* const* d_in, const int* in_sizes, int n_in,
                              void* d_out, int out_size)
{
    const float* input  = (const float*)d_in[0];   // (B, S, L) f32
    const int*   label  = (const int*)  d_in[1];   // (B, S) i32
    const int*   length = (const int*)  d_in[2];   // (B,) i32
    const float* trans  = (const float*)d_in[3];   // (L, L) f32
    float* out = (float*)d_out;                    // (B, 1) f32

    const int B = in_sizes[2];
    const int S = in_sizes[1] / B;

    const int npairs = (B + 1) / 2;
    const int nfirst = npairs > 148 ? 148 : npairs;

    sort_len_kernel<<<1, 1024>>>(length, B, S);
    crf_forward_kernel<<<npairs, 512>>>(input, label, length, trans, out,
                                        S, B, npairs, nfirst);
}

// round 15
// speedup vs baseline: 1.4613x; 1.4613x over previous
#include <cuda_runtime.h>
#include <math.h>
#include <limits.h>

// CRF loss: out[b] = logZ(b) - label_score(b).  B=512, S=512, L=128.
//
// Scaled linear-space forward recursion, TWO adjacent-length batches per
// 512-thread block at 2 CTAs/SM (32 warps/SM).
// U layout (THE R15 fix): float i of each (buf,g) vector lives at index
// 20*(i>>4) + (i&15)  (16-float groups, stride 20). Read instr k then
// touches banks {0,20,8,28,16,4,24,12}+4k -- all distinct -> every
// LDS.128 is ONE 128B wavefront (R14's skew had 2-way conflicts on all
// 8 hot loads). Stores from the 16 owner lanes hit 4 disjoint bank
// quads -> 1 wavefront.
// Lane bits: rg=l&7 -> rows [16rg,16rg+16) (4x LDS.128/batch);
// owner routing g=l&1 (batch), myc=(l>>1)&1 (col half), dup=(l>>2)&1;
// cs=(l>>3)&3 -> cols {4w+cs, 4w+cs+64}, E = 16 f32x2 regs/thread (one
// E copy per block). 4-shfl owner-directed butterfly lands each (g,jo)
// sum on its owner lane; every lane owns one scalar stream. ONE
// __syncthreads per pair-step. Pairs sorted longest-first with
// co-residency remap.

#define LDIM 128

__device__ int d_perm[1024];

__device__ __forceinline__ unsigned long long pack_f32x2(float lo, float hi) {
    unsigned long long r;
    asm("mov.b64 %0, {%1, %2};" : "=l"(r) : "f"(lo), "f"(hi));
    return r;
}
__device__ __forceinline__ void unpack_f32x2(unsigned long long v, float& lo, float& hi) {
    asm("mov.b64 {%0, %1}, %2;" : "=f"(lo), "=f"(hi) : "l"(v));
}
__device__ __forceinline__ unsigned long long fma_f32x2(unsigned long long a,
                                                        unsigned long long b,
                                                        unsigned long long c) {
    unsigned long long d;
    asm("fma.rn.f32x2 %0, %1, %2, %3;" : "=l"(d) : "l"(a), "l"(b), "l"(c));
    return d;
}
__device__ __forceinline__ float rcp_approx(float x) {
    float r;
    asm("rcp.approx.ftz.f32 %0, %1;" : "=f"(r) : "f"(x));
    return r;
}
__device__ __forceinline__ float hsum1(unsigned long long a) {
    float lo, hi;
    unpack_f32x2(a, lo, hi);
    return lo + hi;
}

// ------------- longest-first permutation (bitonic, 1 block) ---------------
__global__ void sort_len_kernel(const int* __restrict__ length, int B, int S)
{
    __shared__ int key[1024];
    __shared__ int val[1024];
    const int t = threadIdx.x;

    int k = INT_MAX;
    if (t < B) {
        int L = length[t];
        L = L < 1 ? 1 : (L > S ? S : L);
        k = -L;               // ascending on -len => longest first
    }
    key[t] = k;
    val[t] = t;
    __syncthreads();

    for (int kk = 2; kk <= 1024; kk <<= 1) {
        for (int s = kk >> 1; s > 0; s >>= 1) {
            int p = t ^ s;
            if (p > t) {
                bool up = ((t & kk) == 0);
                int kt = key[t], kp = key[p];
                if ((kt > kp) == up) {
                    key[t] = kp; key[p] = kt;
                    int vt = val[t]; val[t] = val[p]; val[p] = vt;
                }
            }
            __syncthreads();
        }
    }
    if (t < B) d_perm[t] = val[t];
}

// ------------------------------ main kernel --------------------------------
__global__ __launch_bounds__(512, 2)
void crf_forward_kernel(const float* __restrict__ input,
                        const int*   __restrict__ label,
                        const int*   __restrict__ length,
                        const float* __restrict__ trans,
                        float* __restrict__ out,
                        int S, int B, int npairs, int nfirst)
{
    // padded-stride layout: float i at 20*(i>>4) + (i&15); size 156/(buf,g)
    __shared__ __align__(16) float u_sh[2][2][156];
    __shared__ float wred[2][16];
    __shared__ float wlog[2][16];
    __shared__ float s_x00[2];
    __shared__ float s_ls[2];

    const int tid = threadIdx.x;
    const int w   = tid >> 5;            // warp 0..15
    const int l   = tid & 31;
    const int rg  = l & 7;               // rows [16rg, 16rg+16)
    const int g   = l & 1;               // owned batch (post-routing)
    const int myc = (l >> 1) & 1;        // owned column half
    const int dup = (l >> 2) & 1;        // duplicate-owner flag
    const int cs  = (l >> 3) & 3;        // column slot
    const int jc  = 4 * w + cs;          // 0..63
    const int jo  = jc + (myc << 6);     // owned column 0..127
    const int sidx = 20 * (jo >> 4) + (jo & 15);     // padded store index
    const int qi   = 5 * rg;                         // ull2 read base

    const int bid = blockIdx.x;
    const int pid = (bid < nfirst) ? bid : (npairs - 1 - (bid - nfirst));

    const int  b0   = d_perm[2 * pid];
    const bool has1 = (2 * pid + 1 < B);
    const int  b1   = has1 ? d_perm[2 * pid + 1] : b0;

    int len0 = length[b0]; len0 = len0 < 1 ? 1 : (len0 > S ? S : len0);
    int len1 = len0;
    if (has1) { len1 = length[b1]; len1 = len1 < 1 ? 1 : (len1 > S ? S : len1); }
    // sorted order: len0 >= len1.

    const float* xb0 = input + (size_t)b0 * S * LDIM;
    const float* xb1 = input + (size_t)b1 * S * LDIM;
    const int    lenown = g ? len1 : len0;

    // ---------------- label scores (both batches) ----------------------
    #pragma unroll
    for (int gg = 0; gg < 2; gg++) {
        const float* xb = gg ? xb1 : xb0;
        const int* labb = label + (size_t)(gg ? b1 : b0) * S;
        const int  len  = gg ? (has1 ? len1 : 0) : len0;
        float ls = 0.f;
        for (int t = tid; t < len; t += 512) {
            int lab = labb[t];
            ls += xb[(size_t)t * LDIM + lab];
            if (t + 1 < len) ls += trans[lab * LDIM + labb[t + 1]];
        }
        #pragma unroll
        for (int o = 16; o > 0; o >>= 1)
            ls += __shfl_xor_sync(0xffffffffu, ls, o);
        if (l == 0) wred[gg][w] = ls;
    }
    __syncthreads();
    if (tid < 2) {
        float acc = 0.f;
        #pragma unroll
        for (int i = 0; i < 16; i++) acc += wred[tid][i];
        s_ls[tid] = acc;
    }

    // ---- E rows [16rg,16rg+16) of cols {jc, jc+64}: 16 f32x2 regs -----
    unsigned long long E2[2][8];
    #pragma unroll
    for (int c = 0; c < 2; c++) {
        int col = jc + (c << 6);
        #pragma unroll
        for (int k = 0; k < 8; k++) {
            int r0 = 16 * rg + 2 * k;
            E2[c][k] = pack_f32x2(__expf(trans[r0 * LDIM + col]),
                                  __expf(trans[(r0 + 1) * LDIM + col]));
        }
    }

    // ---------------- init U + prefetch --------------------------------
    const float* pj = (g ? xb1 : xb0) + jo;
    float x0 = pj[0];
    if (tid < 2) s_x00[tid] = x0;     // tid0: g0 jo0; tid1: g1 jo0
    __syncthreads();
    float U = __expf(x0 - s_x00[g]);
    if (dup == 0) u_sh[0][g][sidx] = U;

    const int omax = (lenown - 1) << 7;
    int oB = 256 < omax ? 256 : omax;            // offset of xB (t=2)
    int oA = 128 < omax ? 128 : omax;
    float xA = pj[oA];                            // x for t=1
    float xB = pj[oB];                            // x for t=2

    float alog = 0.f;
    __syncthreads();

    int cur = 0;

    // ---------------- forward recursion: t = 1 .. len0-1 ----------------
    for (int t = 1; t < len0; t++) {
        const float r  = rcp_approx(u_sh[cur][g][0]);
        const float ex = __expf(xA);

        xA = xB;
        oB = (oB + 128) < omax ? (oB + 128) : omax;
        xB = pj[oB];

        // partial GEMV, batch-sequential to cap live registers
        float p00, p01, p10, p11;
        {
            const ulonglong2* q = (const ulonglong2*)(&u_sh[cur][0][0]) + qi;
            ulonglong2 u0 = q[0], u1 = q[1], u2 = q[2], u3 = q[3];
            unsigned long long a0 = 0ull, a1 = 0ull;
            a0 = fma_f32x2(u0.x, E2[0][0], a0);
            a1 = fma_f32x2(u0.x, E2[1][0], a1);
            a0 = fma_f32x2(u0.y, E2[0][1], a0);
            a1 = fma_f32x2(u0.y, E2[1][1], a1);
            a0 = fma_f32x2(u1.x, E2[0][2], a0);
            a1 = fma_f32x2(u1.x, E2[1][2], a1);
            a0 = fma_f32x2(u1.y, E2[0][3], a0);
            a1 = fma_f32x2(u1.y, E2[1][3], a1);
            a0 = fma_f32x2(u2.x, E2[0][4], a0);
            a1 = fma_f32x2(u2.x, E2[1][4], a1);
            a0 = fma_f32x2(u2.y, E2[0][5], a0);
            a1 = fma_f32x2(u2.y, E2[1][5], a1);
            a0 = fma_f32x2(u3.x, E2[0][6], a0);
            a1 = fma_f32x2(u3.x, E2[1][6], a1);
            a0 = fma_f32x2(u3.y, E2[0][7], a0);
            a1 = fma_f32x2(u3.y, E2[1][7], a1);
            p00 = hsum1(a0);
            p01 = hsum1(a1);
        }
        {
            const ulonglong2* q = (const ulonglong2*)(&u_sh[cur][1][0]) + qi;
            ulonglong2 u0 = q[0], u1 = q[1], u2 = q[2], u3 = q[3];
            unsigned long long a0 = 0ull, a1 = 0ull;
            a0 = fma_f32x2(u0.x, E2[0][0], a0);
            a1 = fma_f32x2(u0.x, E2[1][0], a1);
            a0 = fma_f32x2(u0.y, E2[0][1], a0);
            a1 = fma_f32x2(u0.y, E2[1][1], a1);
            a0 = fma_f32x2(u1.x, E2[0][2], a0);
            a1 = fma_f32x2(u1.x, E2[1][2], a1);
            a0 = fma_f32x2(u1.y, E2[0][3], a0);
            a1 = fma_f32x2(u1.y, E2[1][3], a1);
            a0 = fma_f32x2(u2.x, E2[0][4], a0);
            a1 = fma_f32x2(u2.x, E2[1][4], a1);
            a0 = fma_f32x2(u2.y, E2[0][5], a0);
            a1 = fma_f32x2(u2.y, E2[1][5], a1);
            a0 = fma_f32x2(u3.x, E2[0][6], a0);
            a1 = fma_f32x2(u3.x, E2[1][6], a1);
            a0 = fma_f32x2(u3.y, E2[0][7], a0);
            a1 = fma_f32x2(u3.y, E2[1][7], a1);
            p10 = hsum1(a0);
            p11 = hsum1(a1);
        }

        // owner-directed butterfly over lane bits 0..2 (4 shfl total)
        float k0 = g ? p10 : p00;
        float m0 = g ? p00 : p10;
        float k1 = g ? p11 : p01;
        float m1 = g ? p01 : p11;
        k0 += __shfl_xor_sync(0xffffffffu, m0, 1);
        k1 += __shfl_xor_sync(0xffffffffu, m1, 1);
        float kk = myc ? k1 : k0;
        float mm = myc ? k0 : k1;
        kk += __shfl_xor_sync(0xffffffffu, mm, 2);
        kk += __shfl_xor_sync(0xffffffffu, kk, 4);

        float Un = kk * (r * ex);
        U = (t < lenown) ? Un : U;
        if (dup == 0) u_sh[cur ^ 1][g][sidx] = U;
        if (l < 2 && w == (t & 15) && t < lenown)
            alog += __logf(r);                     // lane0:g0, lane1:g1
        cur ^= 1;
        __syncthreads();
    }

    // ---------------- outputs ------------------------------------------
    float es0 = (g == 0 && dup == 0) ? U : 0.f;
    float es1 = (g == 1 && dup == 0) ? U : 0.f;
    #pragma unroll
    for (int oo = 16; oo > 0; oo >>= 1) {
        es0 += __shfl_xor_sync(0xffffffffu, es0, oo);
        es1 += __shfl_xor_sync(0xffffffffu, es1, oo);
    }
    if (l == 0) { wred[0][w] = es0; wred[1][w] = es1; wlog[0][w] = alog; }
    if (l == 1) { wlog[1][w] = alog; }
    __syncthreads();
    if (tid == 0) {
        float ss0 = 0.f, al0 = 0.f;
        #pragma unroll
        for (int i = 0; i < 16; i++) { ss0 += wred[0][i]; al0 += wlog[0][i]; }
        out[b0] = s_x00[0] - al0 + logf(ss0) - s_ls[0];
        if (has1) {
            float ss1 = 0.f, al1 = 0.f;
            #pragma unroll
            for (int i = 0; i < 16; i++) { ss1 += wred[1][i]; al1 += wlog[1][i]; }
            out[b1] = s_x00[1] - al1 + logf(ss1) - s_ls[1];
        }
    }
}

extern "C" void kernel_launch(void* const* d_in, const int* in_sizes, int n_in,
                              void* d_out, int out_size)
{
    const float* input  = (const float*)d_in[0];   // (B, S, L) f32
    const int*   label  = (const int*)  d_in[1];   // (B, S) i32
    const int*   length = (const int*)  d_in[2];   // (B,) i32
    const float* trans  = (const float*)d_in[3];   // (L, L) f32
    float* out = (float*)d_out;                    // (B, 1) f32

    const int B = in_sizes[2];
    const int S = in_sizes[1] / B;

    const int npairs = (B + 1) / 2;
    const int nfirst = npairs > 148 ? 148 : npairs;

    sort_len_kernel<<<1, 1024>>>(length, B, S);
    crf_forward_kernel<<<npairs, 512>>>(input, label, length, trans, out,
                                        S, B, npairs, nfirst);
}

// round 16
// speedup vs baseline: 1.9414x; 1.3285x over previous
#include <cuda_runtime.h>
#include <math.h>
#include <limits.h>

// CRF loss: out[b] = logZ(b) - label_score(b).  B=512, S=512, L=128.
//
// R10 core (verified 182.8us) + critical-path scheduling:
//   grid = 296 CTAs (exactly 2/SM). The 80 LONGEST sequences run as TRUE
//   singles (uniform `if (has1)` skips the whole batch-1 GEMV: ~45% fewer
//   loop instructions on the critical CTAs). Remaining 432 batches form
//   216 adjacent pairs; heavy pairs (p=0..67) on bids 80..147, light
//   pairs reversed on bids 148..295 so the classic (bid, bid+148)
//   co-residency puts near-constant load (~514-594 step-equivalents) on
//   every SM. Inner loop identical to R10: thread holds E rows
//   [32q,32q+32) of cols {jp,jp+64} (32 f32x2), each LDS.128 feeds 4
//   FFMA2, 8-shfl quarter reduction, every lane owns one (batch,col)
//   scalar stream, ONE __syncthreads per step.

#define LDIM 128

__device__ int d_perm[1024];

__device__ __forceinline__ unsigned long long pack_f32x2(float lo, float hi) {
    unsigned long long r;
    asm("mov.b64 %0, {%1, %2};" : "=l"(r) : "f"(lo), "f"(hi));
    return r;
}
__device__ __forceinline__ void unpack_f32x2(unsigned long long v, float& lo, float& hi) {
    asm("mov.b64 {%0, %1}, %2;" : "=f"(lo), "=f"(hi) : "l"(v));
}
__device__ __forceinline__ unsigned long long fma_f32x2(unsigned long long a,
                                                        unsigned long long b,
                                                        unsigned long long c) {
    unsigned long long d;
    asm("fma.rn.f32x2 %0, %1, %2, %3;" : "=l"(d) : "l"(a), "l"(b), "l"(c));
    return d;
}
__device__ __forceinline__ unsigned long long add_f32x2(unsigned long long a,
                                                        unsigned long long b) {
    unsigned long long d;
    asm("add.rn.f32x2 %0, %1, %2;" : "=l"(d) : "l"(a), "l"(b));
    return d;
}
__device__ __forceinline__ float rcp_approx(float x) {
    float r;
    asm("rcp.approx.ftz.f32 %0, %1;" : "=f"(r) : "f"(x));
    return r;
}
__device__ __forceinline__ float hsum2(unsigned long long a, unsigned long long b) {
    unsigned long long s = add_f32x2(a, b);
    float lo, hi;
    unpack_f32x2(s, lo, hi);
    return lo + hi;
}

// ------------- longest-first permutation (bitonic, 1 block) ---------------
__global__ void sort_len_kernel(const int* __restrict__ length, int B, int S)
{
    __shared__ int key[1024];
    __shared__ int val[1024];
    const int t = threadIdx.x;

    int k = INT_MAX;
    if (t < B) {
        int L = length[t];
        L = L < 1 ? 1 : (L > S ? S : L);
        k = -L;               // ascending on -len => longest first
    }
    key[t] = k;
    val[t] = t;
    __syncthreads();

    for (int kk = 2; kk <= 1024; kk <<= 1) {
        for (int s = kk >> 1; s > 0; s >>= 1) {
            int p = t ^ s;
            if (p > t) {
                bool up = ((t & kk) == 0);
                int kt = key[t], kp = key[p];
                if ((kt > kp) == up) {
                    key[t] = kp; key[p] = kt;
                    int vt = val[t]; val[t] = val[p]; val[p] = vt;
                }
            }
            __syncthreads();
        }
    }
    if (t < B) d_perm[t] = val[t];
}

// ------------------------------ main kernel --------------------------------
__global__ __launch_bounds__(256, 2)
void crf_forward_kernel(const float* __restrict__ input,
                        const int*   __restrict__ label,
                        const int*   __restrict__ length,
                        const float* __restrict__ trans,
                        float* __restrict__ out,
                        int S, int B, int nsingle, int nblk, int npairs)
{
    __shared__ __align__(16) float u_sh[2][2][144];   // [buf][g][state]
    __shared__ float wred[2][8];
    __shared__ float wlog[2][8];
    __shared__ float s_x00[2];
    __shared__ float s_ls[2];

    const int tid = threadIdx.x;
    const int w   = tid >> 5;
    const int l   = tid & 31;
    const int q   = l >> 3;              // row quarter / ownership code
    const int jp  = w * 8 + (l & 7);     // column pair base 0..63
    const int g   = q >> 1;              // owned batch
    const int jo  = jp + ((q & 1) << 6); // owned column

    // ---- schedule: singles on bids [0,nsingle); heavy pairs p=bid-nsingle
    // on [nsingle,148); light pairs reversed on [148, nblk) ----
    const int bid = blockIdx.x;
    const bool has1 = (bid >= nsingle);
    int p = bid - nsingle;
    if (bid >= 148 && nblk > 148) p = (npairs - 1) - (bid - 148);

    const int b0 = has1 ? d_perm[nsingle + 2 * p]     : d_perm[bid];
    const int b1 = has1 ? d_perm[nsingle + 2 * p + 1] : b0;

    int len0 = length[b0]; len0 = len0 < 1 ? 1 : (len0 > S ? S : len0);
    int len1 = len0;
    if (has1) { len1 = length[b1]; len1 = len1 < 1 ? 1 : (len1 > S ? S : len1); }
    // sorted adjacent ranks: len0 >= len1.

    const float* xb0 = input + (size_t)b0 * S * LDIM;
    const float* xb1 = input + (size_t)b1 * S * LDIM;
    const float* xbg = g ? xb1 : xb0;
    const int    lenown = g ? len1 : len0;

    // ---------------- label scores (both batches) ----------------------
    #pragma unroll
    for (int gg = 0; gg < 2; gg++) {
        const float* xb = gg ? xb1 : xb0;
        const int* labb = label + (size_t)(gg ? b1 : b0) * S;
        const int  len  = gg ? (has1 ? len1 : 0) : len0;
        float ls = 0.f;
        for (int t = tid; t < len; t += 256) {
            int lab = labb[t];
            ls += xb[(size_t)t * LDIM + lab];
            if (t + 1 < len) ls += trans[lab * LDIM + labb[t + 1]];
        }
        #pragma unroll
        for (int o = 16; o > 0; o >>= 1)
            ls += __shfl_xor_sync(0xffffffffu, ls, o);
        if (l == 0) wred[gg][w] = ls;
    }
    __syncthreads();
    if (tid < 2) {
        float acc = 0.f;
        #pragma unroll
        for (int i = 0; i < 8; i++) acc += wred[tid][i];
        s_ls[tid] = acc;
    }

    // --- E rows [32q,32q+32) of columns jp and jp+64: 32 f32x2 regs ----
    unsigned long long E2A[16], E2B[16];
    #pragma unroll
    for (int k = 0; k < 16; k++) {
        int i0 = 32 * q + 2 * k;
        E2A[k] = pack_f32x2(__expf(trans[(i0)     * LDIM + jp]),
                            __expf(trans[(i0 + 1) * LDIM + jp]));
        E2B[k] = pack_f32x2(__expf(trans[(i0)     * LDIM + jp + 64]),
                            __expf(trans[(i0 + 1) * LDIM + jp + 64]));
    }

    // ---------------- init U (every lane owns one (g, jo) stream) -------
    const int wido = jo + ((jo >> 5) << 2);   // skewed store index
    const float* pj = xbg + jo;
    float x0 = pj[0];
    if (tid == 0)  s_x00[0] = x0;             // g=0, jo=0
    if (tid == 16) s_x00[1] = x0;             // g=1, jo=0
    __syncthreads();
    float U = __expf(x0 - s_x00[g]);
    u_sh[0][g][wido] = U;

    const int omax = (lenown - 1) * LDIM;
    int o1 = LDIM     < omax ? LDIM     : omax;
    int o2 = 2 * LDIM < omax ? 2 * LDIM : omax;
    float xA = pj[o1];                         // x for t=1
    float xB = pj[o2];                         // x for t=2

    float alog = 0.f;                          // rotating owner lanes only
    __syncthreads();

    int cur = 0;

    // ---------------- forward recursion: t = 1 .. len0-1 ----------------
    for (int t = 1; t < len0; t++) {
        const int nxt = cur ^ 1;
        const float r  = rcp_approx(u_sh[cur][g][0]);   // own batch's U[0]
        const float ex = __expf(xA);

        // rotate prefetch (x for t+2)
        xA = xB;
        int on = (t + 2) * LDIM;
        if (on > omax) on = omax;
        xB = pj[on];

        // partial GEMVs: 8 LDS.128 per batch, each feeding 4 FFMA2
        const ulonglong2* p0 = (const ulonglong2*)(u_sh[cur][0] + 36 * q);
        unsigned long long aA0 = 0ull, aA1 = 0ull, aB0 = 0ull, aB1 = 0ull;
        unsigned long long cA0 = 0ull, cA1 = 0ull, cB0 = 0ull, cB1 = 0ull;
        #pragma unroll
        for (int c = 0; c < 8; c++) {
            ulonglong2 ua = p0[c];
            aA0 = fma_f32x2(ua.x, E2A[2 * c + 0], aA0);
            aA1 = fma_f32x2(ua.y, E2A[2 * c + 1], aA1);
            aB0 = fma_f32x2(ua.x, E2B[2 * c + 0], aB0);
            aB1 = fma_f32x2(ua.y, E2B[2 * c + 1], aB1);
        }
        if (has1) {                            // uniform branch per CTA
            const ulonglong2* p1 = (const ulonglong2*)(u_sh[cur][1] + 36 * q);
            #pragma unroll
            for (int c = 0; c < 8; c++) {
                ulonglong2 va = p1[c];
                cA0 = fma_f32x2(va.x, E2A[2 * c + 0], cA0);
                cA1 = fma_f32x2(va.y, E2A[2 * c + 1], cA1);
                cB0 = fma_f32x2(va.x, E2B[2 * c + 0], cB0);
                cB1 = fma_f32x2(va.y, E2B[2 * c + 1], cB1);
            }
        }
        float s0A = hsum2(aA0, aA1);   // batch0, col jp   (quarter partial)
        float s0B = hsum2(aB0, aB1);   // batch0, col jp+64
        float s1A = hsum2(cA0, cA1);   // batch1, col jp
        float s1B = hsum2(cB0, cB1);   // batch1, col jp+64

        // reduce over quarters (lane bits 3,4)
        #pragma unroll
        for (int oo = 8; oo <= 16; oo <<= 1) {
            s0A += __shfl_xor_sync(0xffffffffu, s0A, oo);
            s0B += __shfl_xor_sync(0xffffffffu, s0B, oo);
            s1A += __shfl_xor_sync(0xffffffffu, s1A, oo);
            s1B += __shfl_xor_sync(0xffffffffu, s1B, oo);
        }

        // each lane picks its owned (batch, column) sum
        float sb0 = (q & 1) ? s0B : s0A;
        float sb1 = (q & 1) ? s1B : s1A;
        float sown = g ? sb1 : sb0;

        float Un = sown * (r * ex);
        bool  act = (t < lenown);            // batch-1 freezes at len1
        U = act ? Un : U;
        u_sh[nxt][g][wido] = U;
        if ((l & 15) == 0 && w == (t & 7) && act)   // lanes 0,16 of warp t&7
            alog += __logf(r);
        cur = nxt;
        __syncthreads();
    }

    // ---------------- outputs ------------------------------------------
    float es0 = (g == 0) ? U : 0.f;
    float es1 = (g == 1) ? U : 0.f;
    #pragma unroll
    for (int oo = 16; oo > 0; oo >>= 1) {
        es0 += __shfl_xor_sync(0xffffffffu, es0, oo);
        es1 += __shfl_xor_sync(0xffffffffu, es1, oo);
    }
    if (l == 0)  { wred[0][w] = es0; wred[1][w] = es1; wlog[0][w] = alog; }
    if (l == 16) { wlog[1][w] = alog; }
    __syncthreads();
    if (tid == 0) {
        float ss0 = 0.f, al0 = 0.f;
        #pragma unroll
        for (int i = 0; i < 8; i++) { ss0 += wred[0][i]; al0 += wlog[0][i]; }
        out[b0] = s_x00[0] - al0 + logf(ss0) - s_ls[0];
        if (has1) {
            float ss1 = 0.f, al1 = 0.f;
            #pragma unroll
            for (int i = 0; i < 8; i++) { ss1 += wred[1][i]; al1 += wlog[1][i]; }
            out[b1] = s_x00[1] - al1 + logf(ss1) - s_ls[1];
        }
    }
}

extern "C" void kernel_launch(void* const* d_in, const int* in_sizes, int n_in,
                              void* d_out, int out_size)
{
    const float* input  = (const float*)d_in[0];   // (B, S, L) f32
    const int*   label  = (const int*)  d_in[1];   // (B, S) i32
    const int*   length = (const int*)  d_in[2];   // (B,) i32
    const float* trans  = (const float*)d_in[3];   // (L, L) f32
    float* out = (float*)d_out;                    // (B, 1) f32

    const int B = in_sizes[2];
    const int S = in_sizes[1] / B;

    const int SLOTS = 296;                          // 2 CTAs x 148 SMs
    int nblk, nsingle;
    if (B <= SLOTS) {
        nblk = B;       nsingle = B;                // every batch solo
    } else if (B <= 2 * SLOTS) {
        nblk = SLOTS;   nsingle = 2 * SLOTS - B;    // B=512 -> 80 singles
    } else {
        nblk = (B + 1) / 2;
        nsingle = 2 * nblk - B;
    }
    const int npairs = nblk - nsingle;

    sort_len_kernel<<<1, 1024>>>(length, B, S);
    crf_forward_kernel<<<nblk, 256>>>(input, label, length, trans, out,
                                      S, B, nsingle, nblk, npairs);
}

// round 17
// speedup vs baseline: 2.1481x; 1.1065x over previous
#include <cuda_runtime.h>
#include <math.h>
#include <limits.h>

// CRF loss: out[b] = logZ(b) - label_score(b).  B=512, S=512, L=128.
//
// R16 core + balanced co-residency + split loops.
// Grid = 296 CTAs (2/SM, classic placement pairs bid with bid+148):
//   bids   0..79  : singles, sorted ranks 0..79 (the 80 longest)
//   bids  80..147 : heavy pairs p = bid-80           (p = 0..67)
//   bids 148..227 : mid pairs  p = 147-(bid-148)     (p = 147..68)
//   bids 228..295 : light pairs p = 215-(bid-228)    (p = 215..148)
// -> SM loads: heavy+light ~434 const; single+mid ~445..556. Balanced.
// Inner loop (R10-verified): thread (q=l>>3, jp=8w+(l&7)) holds E rows
// [32q,32q+32) of cols {jp,jp+64} as 32 f32x2 regs; each LDS.128 of U
// feeds 4 FFMA2; 2-stage shfl reduction; every lane owns one (batch,col)
// scalar stream; ONE __syncthreads per step.
// Split loops: dual while t<len1, then single-batch to len0 (skips the
// entire batch-1 GEMV: 8 LDS + 32 FFMA2 + 4 shfl per tail step).

#define LDIM 128

__device__ int d_perm[1024];

__device__ __forceinline__ unsigned long long pack_f32x2(float lo, float hi) {
    unsigned long long r;
    asm("mov.b64 %0, {%1, %2};" : "=l"(r) : "f"(lo), "f"(hi));
    return r;
}
__device__ __forceinline__ void unpack_f32x2(unsigned long long v, float& lo, float& hi) {
    asm("mov.b64 {%0, %1}, %2;" : "=f"(lo), "=f"(hi) : "l"(v));
}
__device__ __forceinline__ unsigned long long fma_f32x2(unsigned long long a,
                                                        unsigned long long b,
                                                        unsigned long long c) {
    unsigned long long d;
    asm("fma.rn.f32x2 %0, %1, %2, %3;" : "=l"(d) : "l"(a), "l"(b), "l"(c));
    return d;
}
__device__ __forceinline__ unsigned long long add_f32x2(unsigned long long a,
                                                        unsigned long long b) {
    unsigned long long d;
    asm("add.rn.f32x2 %0, %1, %2;" : "=l"(d) : "l"(a), "l"(b));
    return d;
}
__device__ __forceinline__ float rcp_approx(float x) {
    float r;
    asm("rcp.approx.ftz.f32 %0, %1;" : "=f"(r) : "f"(x));
    return r;
}
__device__ __forceinline__ float hsum2(unsigned long long a, unsigned long long b) {
    unsigned long long s = add_f32x2(a, b);
    float lo, hi;
    unpack_f32x2(s, lo, hi);
    return lo + hi;
}

// ------------- longest-first permutation (bitonic, 1 block) ---------------
__global__ void sort_len_kernel(const int* __restrict__ length, int B, int S)
{
    __shared__ int key[1024];
    __shared__ int val[1024];
    const int t = threadIdx.x;

    int k = INT_MAX;
    if (t < B) {
        int L = length[t];
        L = L < 1 ? 1 : (L > S ? S : L);
        k = -L;               // ascending on -len => longest first
    }
    key[t] = k;
    val[t] = t;
    __syncthreads();

    for (int kk = 2; kk <= 1024; kk <<= 1) {
        for (int s = kk >> 1; s > 0; s >>= 1) {
            int p = t ^ s;
            if (p > t) {
                bool up = ((t & kk) == 0);
                int kt = key[t], kp = key[p];
                if ((kt > kp) == up) {
                    key[t] = kp; key[p] = kt;
                    int vt = val[t]; val[t] = val[p]; val[p] = vt;
                }
            }
            __syncthreads();
        }
    }
    if (t < B) d_perm[t] = val[t];
}

// ------------------------------ main kernel --------------------------------
__global__ __launch_bounds__(256, 2)
void crf_forward_kernel(const float* __restrict__ input,
                        const int*   __restrict__ label,
                        const int*   __restrict__ length,
                        const float* __restrict__ trans,
                        float* __restrict__ out,
                        int S, int B, int nsingle, int nblk, int npairs)
{
    __shared__ __align__(16) float u_sh[2][2][144];   // [buf][g][state]
    __shared__ float wred[2][8];
    __shared__ float wlog[2][8];
    __shared__ float s_x00[2];
    __shared__ float s_ls[2];

    const int tid = threadIdx.x;
    const int w   = tid >> 5;
    const int l   = tid & 31;
    const int q   = l >> 3;              // row quarter / ownership code
    const int jp  = w * 8 + (l & 7);     // column pair base 0..63
    const int g   = q >> 1;              // owned batch
    const int jo  = jp + ((q & 1) << 6); // owned column

    // ---- balanced schedule (see header) ----
    const int bid = blockIdx.x;
    const bool has1 = (bid >= nsingle);
    int p;
    if (nblk == 296 && nsingle == 80) {
        if      (bid < 148) p = bid - 80;            // heavy 0..67
        else if (bid < 228) p = 147 - (bid - 148);   // mid 147..68
        else                p = 215 - (bid - 228);   // light 215..148
    } else {
        p = bid - nsingle;
    }

    const int b0 = has1 ? d_perm[nsingle + 2 * p]     : d_perm[bid];
    const int b1 = has1 ? d_perm[nsingle + 2 * p + 1] : b0;

    int len0 = length[b0]; len0 = len0 < 1 ? 1 : (len0 > S ? S : len0);
    int len1 = 1;
    if (has1) { len1 = length[b1]; len1 = len1 < 1 ? 1 : (len1 > S ? S : len1); }
    // sorted adjacent ranks: len0 >= len1 when has1.

    const float* xb0 = input + (size_t)b0 * S * LDIM;
    const float* xb1 = input + (size_t)b1 * S * LDIM;
    const float* xbg = g ? xb1 : xb0;
    const int    lenown = g ? len1 : len0;

    // ---------------- label scores (both batches) ----------------------
    #pragma unroll
    for (int gg = 0; gg < 2; gg++) {
        const float* xb = gg ? xb1 : xb0;
        const int* labb = label + (size_t)(gg ? b1 : b0) * S;
        const int  len  = gg ? (has1 ? len1 : 0) : len0;
        float ls = 0.f;
        for (int t = tid; t < len; t += 256) {
            int lab = labb[t];
            ls += xb[(size_t)t * LDIM + lab];
            if (t + 1 < len) ls += trans[lab * LDIM + labb[t + 1]];
        }
        #pragma unroll
        for (int o = 16; o > 0; o >>= 1)
            ls += __shfl_xor_sync(0xffffffffu, ls, o);
        if (l == 0) wred[gg][w] = ls;
    }
    __syncthreads();
    if (tid < 2) {
        float acc = 0.f;
        #pragma unroll
        for (int i = 0; i < 8; i++) acc += wred[tid][i];
        s_ls[tid] = acc;
    }

    // --- E rows [32q,32q+32) of columns jp and jp+64: 32 f32x2 regs ----
    unsigned long long E2A[16], E2B[16];
    #pragma unroll
    for (int k = 0; k < 16; k++) {
        int i0 = 32 * q + 2 * k;
        E2A[k] = pack_f32x2(__expf(trans[(i0)     * LDIM + jp]),
                            __expf(trans[(i0 + 1) * LDIM + jp]));
        E2B[k] = pack_f32x2(__expf(trans[(i0)     * LDIM + jp + 64]),
                            __expf(trans[(i0 + 1) * LDIM + jp + 64]));
    }

    // ---------------- init U (every lane owns one (g, jo) stream) -------
    const int wido = jo + ((jo >> 5) << 2);   // skewed store index
    const float* pj = xbg + jo;
    float x0 = pj[0];
    if (tid == 0)  s_x00[0] = x0;             // g=0, jo=0
    if (tid == 16) s_x00[1] = x0;             // g=1, jo=0
    __syncthreads();
    float U = __expf(x0 - s_x00[g]);
    u_sh[0][g][wido] = U;

    const int omax = (lenown - 1) * LDIM;
    int o1 = LDIM     < omax ? LDIM     : omax;
    int o2 = 2 * LDIM < omax ? 2 * LDIM : omax;
    float xA = pj[o1];                         // x for t=1
    float xB = pj[o2];                         // x for t=2

    float alog = 0.f;                          // rotating owner lanes only
    __syncthreads();

    int cur = 0;
    int t = 1;

    // ------------- loop A: both batches active (t < len1) ---------------
    if (has1)
    for (; t < len1; t++) {
        const int nxt = cur ^ 1;
        const float r  = rcp_approx(u_sh[cur][g][0]);   // own batch's U[0]
        const float ex = __expf(xA);

        xA = xB;
        int on = (t + 2) * LDIM;
        if (on > omax) on = omax;
        xB = pj[on];

        const ulonglong2* p0 = (const ulonglong2*)(u_sh[cur][0] + 36 * q);
        const ulonglong2* p1 = (const ulonglong2*)(u_sh[cur][1] + 36 * q);
        unsigned long long aA0 = 0ull, aA1 = 0ull, aB0 = 0ull, aB1 = 0ull;
        unsigned long long cA0 = 0ull, cA1 = 0ull, cB0 = 0ull, cB1 = 0ull;
        #pragma unroll
        for (int c = 0; c < 8; c++) {
            ulonglong2 ua = p0[c];
            ulonglong2 va = p1[c];
            aA0 = fma_f32x2(ua.x, E2A[2 * c + 0], aA0);
            aA1 = fma_f32x2(ua.y, E2A[2 * c + 1], aA1);
            aB0 = fma_f32x2(ua.x, E2B[2 * c + 0], aB0);
            aB1 = fma_f32x2(ua.y, E2B[2 * c + 1], aB1);
            cA0 = fma_f32x2(va.x, E2A[2 * c + 0], cA0);
            cA1 = fma_f32x2(va.y, E2A[2 * c + 1], cA1);
            cB0 = fma_f32x2(va.x, E2B[2 * c + 0], cB0);
            cB1 = fma_f32x2(va.y, E2B[2 * c + 1], cB1);
        }
        float s0A = hsum2(aA0, aA1);
        float s0B = hsum2(aB0, aB1);
        float s1A = hsum2(cA0, cA1);
        float s1B = hsum2(cB0, cB1);

        #pragma unroll
        for (int oo = 8; oo <= 16; oo <<= 1) {
            s0A += __shfl_xor_sync(0xffffffffu, s0A, oo);
            s0B += __shfl_xor_sync(0xffffffffu, s0B, oo);
            s1A += __shfl_xor_sync(0xffffffffu, s1A, oo);
            s1B += __shfl_xor_sync(0xffffffffu, s1B, oo);
        }

        float sb0 = (q & 1) ? s0B : s0A;
        float sb1 = (q & 1) ? s1B : s1A;
        float sown = g ? sb1 : sb0;

        U = sown * (r * ex);
        u_sh[nxt][g][wido] = U;
        if ((l & 15) == 0 && w == (t & 7))   // lanes 0,16 of warp t&7
            alog += __logf(r);
        cur = nxt;
        __syncthreads();
    }

    // ------------- loop B: only batch 0 active (t < len0) ---------------
    for (; t < len0; t++) {
        const int nxt = cur ^ 1;
        const float r  = rcp_approx(u_sh[cur][0][0]);
        const float ex = __expf(xA);

        xA = xB;
        int on = (t + 2) * LDIM;
        if (on > omax) on = omax;
        xB = pj[on];

        const ulonglong2* p0 = (const ulonglong2*)(u_sh[cur][0] + 36 * q);
        unsigned long long aA0 = 0ull, aA1 = 0ull, aB0 = 0ull, aB1 = 0ull;
        #pragma unroll
        for (int c = 0; c < 8; c++) {
            ulonglong2 ua = p0[c];
            aA0 = fma_f32x2(ua.x, E2A[2 * c + 0], aA0);
            aA1 = fma_f32x2(ua.y, E2A[2 * c + 1], aA1);
            aB0 = fma_f32x2(ua.x, E2B[2 * c + 0], aB0);
            aB1 = fma_f32x2(ua.y, E2B[2 * c + 1], aB1);
        }
        float s0A = hsum2(aA0, aA1);
        float s0B = hsum2(aB0, aB1);

        #pragma unroll
        for (int oo = 8; oo <= 16; oo <<= 1) {
            s0A += __shfl_xor_sync(0xffffffffu, s0A, oo);
            s0B += __shfl_xor_sync(0xffffffffu, s0B, oo);
        }

        float sb0 = (q & 1) ? s0B : s0A;

        if (g == 0) {
            U = sb0 * (r * ex);
            u_sh[nxt][0][wido] = U;
        }
        if (l == 0 && w == (t & 7))          // lane 0 of warp t&7
            alog += __logf(r);
        cur = nxt;
        __syncthreads();
    }

    // ---------------- outputs ------------------------------------------
    float es0 = (g == 0) ? U : 0.f;
    float es1 = (g == 1) ? U : 0.f;
    #pragma unroll
    for (int oo = 16; oo > 0; oo >>= 1) {
        es0 += __shfl_xor_sync(0xffffffffu, es0, oo);
        es1 += __shfl_xor_sync(0xffffffffu, es1, oo);
    }
    if (l == 0)  { wred[0][w] = es0; wred[1][w] = es1; wlog[0][w] = alog; }
    if (l == 16) { wlog[1][w] = alog; }
    __syncthreads();
    if (tid == 0) {
        float ss0 = 0.f, al0 = 0.f;
        #pragma unroll
        for (int i = 0; i < 8; i++) { ss0 += wred[0][i]; al0 += wlog[0][i]; }
        out[b0] = s_x00[0] - al0 + logf(ss0) - s_ls[0];
        if (has1) {
            float ss1 = 0.f, al1 = 0.f;
            #pragma unroll
            for (int i = 0; i < 8; i++) { ss1 += wred[1][i]; al1 += wlog[1][i]; }
            out[b1] = s_x00[1] - al1 + logf(ss1) - s_ls[1];
        }
    }
}

extern "C" void kernel_launch(void* const* d_in, const int* in_sizes, int n_in,
                              void* d_out, int out_size)
{
    const float* input  = (const float*)d_in[0];   // (B, S, L) f32
    const int*   label  = (const int*)  d_in[1];   // (B, S) i32
    const int*   length = (const int*)  d_in[2];   // (B,) i32
    const float* trans  = (const float*)d_in[3];   // (L, L) f32
    float* out = (float*)d_out;                    // (B, 1) f32

    const int B = in_sizes[2];
    const int S = in_sizes[1] / B;

    const int SLOTS = 296;                          // 2 CTAs x 148 SMs
    int nblk, nsingle;
    if (B <= SLOTS) {
        nblk = B;       nsingle = B;                // every batch solo
    } else if (B <= 2 * SLOTS) {
        nblk = SLOTS;   nsingle = 2 * SLOTS - B;    // B=512 -> 80 singles
    } else {
        nblk = (B + 1) / 2;
        nsingle = 2 * nblk - B;
    }
    const int npairs = nblk - nsingle;

    sort_len_kernel<<<1, 1024>>>(length, B, S);
    crf_forward_kernel<<<nblk, 256>>>(input, label, length, trans, out,
                                      S, B, nsingle, nblk, npairs);
}